// round 12
// baseline (speedup 1.0000x reference)
#include <cuda_runtime.h>
#include <cuda_bf16.h>
#include <cstdint>

// Problem constants
#define TLEN   1024
#define SLEN   1024
#define BSZ    16
#define EMB    256
#define NH     8
#define HD     32
#define BH     (BSZ*NH)        // 128
#define MROWS  (TLEN*BSZ)      // 16384
#define QSCALE 0.17677669529663688f   // 1/sqrt(32)

typedef unsigned long long u64;

__device__ __forceinline__ uint32_t smem_u32(const void* p) {
    uint32_t a;
    asm("{ .reg .u64 t; cvta.to.shared.u64 t, %1; cvt.u32.u64 %0, t; }"
        : "=r"(a) : "l"(p));
    return a;
}

// ---- mma.sync helpers (base ISA; sm_103 target has no tcgen05) --------------
__device__ __forceinline__ void ldmx4(uint32_t r[4], uint32_t addr) {
    asm volatile("ldmatrix.sync.aligned.m8n8.x4.shared.b16 {%0,%1,%2,%3}, [%4];"
                 : "=r"(r[0]), "=r"(r[1]), "=r"(r[2]), "=r"(r[3]) : "r"(addr));
}
__device__ __forceinline__ void mma_bf16(float d[4], const uint32_t a[4],
                                         uint32_t b0, uint32_t b1) {
    asm volatile(
        "mma.sync.aligned.m16n8k16.row.col.f32.bf16.bf16.f32 "
        "{%0,%1,%2,%3}, {%4,%5,%6,%7}, {%8,%9}, {%0,%1,%2,%3};"
        : "+f"(d[0]), "+f"(d[1]), "+f"(d[2]), "+f"(d[3])
        : "r"(a[0]), "r"(a[1]), "r"(a[2]), "r"(a[3]), "r"(b0), "r"(b1));
}

// ---------------- scratch (device globals; no allocation allowed) ----------
__device__ float g_QKV[(size_t)MROWS * 768];   // [t*16+b][sec*256+h*32+d], q pre-scaled
__device__ float g_ctx[(size_t)MROWS * EMB];   // [t*16+b][h*32+d]
// bf16 hi/lo splits of Q (scaled) and K, per-bh contiguous: [bh][t or s][32]
__device__ __align__(16) __nv_bfloat16 g_Qh[(size_t)BH*1024*32];
__device__ __align__(16) __nv_bfloat16 g_Ql[(size_t)BH*1024*32];
__device__ __align__(16) __nv_bfloat16 g_Kh[(size_t)BH*1024*32];
__device__ __align__(16) __nv_bfloat16 g_Kl[(size_t)BH*1024*32];

// ---------------- zero kernel ----------------------------------------------
__global__ void zero_f4(float4* __restrict__ p, int n4) {
    int i = blockIdx.x * blockDim.x + threadIdx.x;
    int stride = gridDim.x * blockDim.x;
    float4 z = make_float4(0.f, 0.f, 0.f, 0.f);
    for (; i < n4; i += stride) p[i] = z;
}

// ---------------- bf16-split HMMA GEMM:  out = X.W^T + b --------------------
#define GM_SMEM 65536

__device__ __forceinline__ void conv_store_g(float4 x, char* hi, char* lo,
                                             int row, int kg4) {
    __nv_bfloat162 h01 = __floats2bfloat162_rn(x.x, x.y);
    __nv_bfloat162 h23 = __floats2bfloat162_rn(x.z, x.w);
    float r0 = x.x - __bfloat162float(h01.x);
    float r1 = x.y - __bfloat162float(h01.y);
    float r2 = x.z - __bfloat162float(h23.x);
    float r3 = x.w - __bfloat162float(h23.y);
    __nv_bfloat162 l01 = __floats2bfloat162_rn(r0, r1);
    __nv_bfloat162 l23 = __floats2bfloat162_rn(r2, r3);
    int c  = kg4 >> 3;
    int sw = row * 128 + ((c ^ (row & 7)) << 4) + ((kg4 & 7) * 2);
    u64 hp = (u64)(*reinterpret_cast<uint32_t*>(&h01)) |
             ((u64)(*reinterpret_cast<uint32_t*>(&h23)) << 32);
    u64 lp = (u64)(*reinterpret_cast<uint32_t*>(&l01)) |
             ((u64)(*reinterpret_cast<uint32_t*>(&l23)) << 32);
    *reinterpret_cast<u64*>(hi + sw) = hp;
    *reinterpret_cast<u64*>(lo + sw) = lp;
}

template<int MODE>
__global__ __launch_bounds__(256)
void gemm_mma(const float* __restrict__ Xq, const float* __restrict__ Xk,
              const float* __restrict__ Xv, const float* __restrict__ W,
              const float* __restrict__ bias, float* __restrict__ outp)
{
    extern __shared__ __align__(128) char smem[];
    char* Ah = smem;
    char* Al = smem + 16384;
    char* Bh = smem + 32768;
    char* Bl = smem + 49152;

    const int tid  = threadIdx.x;
    const int lane = tid & 31;
    const int wid  = tid >> 5;
    const int mw   = (wid & 3) * 32;
    const int nw   = (wid >> 2) * 64;
    const int n0 = blockIdx.x * 128;
    const int m0 = blockIdx.y * 128;

    const float* X;
    if (MODE == 0) {
        int sec = n0 >> 8;
        X = (sec == 0) ? Xq : (sec == 1 ? Xk : Xv);
    } else {
        X = g_ctx;
    }

    const uint32_t sA = smem_u32(Ah), sAl = smem_u32(Al);
    const uint32_t sB = smem_u32(Bh), sBl = smem_u32(Bl);

    float d[2][8][4];
#pragma unroll
    for (int mt = 0; mt < 2; mt++)
#pragma unroll
        for (int nt = 0; nt < 8; nt++)
#pragma unroll
            for (int j = 0; j < 4; j++) d[mt][nt][j] = 0.f;

    const int arow = lane & 15;
    const int acs  = lane >> 4;
    const int brow = (lane & 7) + ((lane >> 4) << 3);
    const int bcs  = (lane >> 3) & 1;
    const int lxor = lane & 7;

    for (int kc = 0; kc < 4; kc++) {
#pragma unroll
        for (int g = tid, it = 0; it < 8; g += 256, it++) {
            int row = g >> 4;
            int kg4 = (g & 15) * 4;
            float4 xa = *reinterpret_cast<const float4*>(
                X + (size_t)(m0 + row) * 256 + kc * 64 + kg4);
            conv_store_g(xa, Ah, Al, row, kg4);
            float4 xb = *reinterpret_cast<const float4*>(
                W + (size_t)(n0 + row) * 256 + kc * 64 + kg4);
            conv_store_g(xb, Bh, Bl, row, kg4);
        }
        __syncthreads();

#pragma unroll
        for (int ks = 0; ks < 4; ks++) {
            uint32_t ah[2][4], al[2][4], bh[4][4], bl[4][4];
#pragma unroll
            for (int mt = 0; mt < 2; mt++) {
                int row = mw + mt * 16 + arow;
                uint32_t off = (uint32_t)(row * 128 + (((2 * ks + acs) ^ lxor) << 4));
                ldmx4(ah[mt], sA + off);
                ldmx4(al[mt], sAl + off);
            }
#pragma unroll
            for (int nt4 = 0; nt4 < 4; nt4++) {
                int row = nw + nt4 * 16 + brow;
                uint32_t off = (uint32_t)(row * 128 + (((2 * ks + bcs) ^ lxor) << 4));
                ldmx4(bh[nt4], sB + off);
                ldmx4(bl[nt4], sBl + off);
            }
#pragma unroll
            for (int mt = 0; mt < 2; mt++)
#pragma unroll
                for (int nt4 = 0; nt4 < 4; nt4++) {
                    mma_bf16(d[mt][nt4 * 2 + 0], ah[mt], bh[nt4][0], bh[nt4][1]);
                    mma_bf16(d[mt][nt4 * 2 + 1], ah[mt], bh[nt4][2], bh[nt4][3]);
                    mma_bf16(d[mt][nt4 * 2 + 0], ah[mt], bl[nt4][0], bl[nt4][1]);
                    mma_bf16(d[mt][nt4 * 2 + 1], ah[mt], bl[nt4][2], bl[nt4][3]);
                    mma_bf16(d[mt][nt4 * 2 + 0], al[mt], bh[nt4][0], bh[nt4][1]);
                    mma_bf16(d[mt][nt4 * 2 + 1], al[mt], bh[nt4][2], bh[nt4][3]);
                }
        }
        __syncthreads();
    }

    // ---- epilogue ----
    const float scl = (MODE == 0 && n0 < 256) ? QSCALE : 1.0f;
    const int qrow = lane >> 2;
    const int qcol = (lane & 3) * 2;
#pragma unroll
    for (int mt = 0; mt < 2; mt++) {
#pragma unroll
        for (int nt = 0; nt < 8; nt++) {
            int n = n0 + nw + nt * 8 + qcol;
            float2 bv = *reinterpret_cast<const float2*>(bias + n);
            int r0 = m0 + mw + mt * 16 + qrow;
#pragma unroll
            for (int hfl = 0; hfl < 2; hfl++) {
                int r = r0 + hfl * 8;
                float2 v;
                v.x = (d[mt][nt][hfl * 2 + 0] + bv.x) * scl;
                v.y = (d[mt][nt][hfl * 2 + 1] + bv.y) * scl;
                float* dst = (MODE == 0) ? (g_QKV + (size_t)r * 768 + n)
                                         : (outp  + (size_t)r * 256 + n);
                *reinterpret_cast<float2*>(dst) = v;
                if (MODE == 0) {
                    int sec = n >> 8;
                    if (sec < 2) {
                        int hh = (n >> 5) & 7, dd = n & 31;
                        int tt = r >> 4,      bb = r & 15;
                        size_t base = (((size_t)(bb * 8 + hh) << 10) + tt) * 32 + dd;
                        __nv_bfloat162 hi2 = __floats2bfloat162_rn(v.x, v.y);
                        float rx = v.x - __bfloat162float(hi2.x);
                        float ry = v.y - __bfloat162float(hi2.y);
                        __nv_bfloat162 lo2 = __floats2bfloat162_rn(rx, ry);
                        if (sec == 0) {
                            *reinterpret_cast<__nv_bfloat162*>(g_Qh + base) = hi2;
                            *reinterpret_cast<__nv_bfloat162*>(g_Ql + base) = lo2;
                        } else {
                            *reinterpret_cast<__nv_bfloat162*>(g_Kh + base) = hi2;
                            *reinterpret_cast<__nv_bfloat162*>(g_Kl + base) = lo2;
                        }
                    }
                }
            }
        }
    }
}

// ---------------- fused attention v3: HMMA scores + compacted ILP AV --------
// 128 blocks (one per bh), 512 threads (16 warps).
// K hi/lo resident in smem (2 s-rows packed per 128B row, XOR swizzle).
// 64 waves of 16 t-rows: MMA phase fills 16x1024 score buffer; epilogue:
// warp w owns row w -> Michelot sparsemax, then stream-compacted (w,s) list
// consumed with 4-way-ILP V loads (breaks the serial LDG chain).
__device__ __forceinline__ uint32_t swz64(int s, int c) {
    int p = s >> 1;
    int j = (((s & 1) << 2) | c) ^ (p & 7);
    return (uint32_t)(p * 128 + j * 16);
}

// smem map: sKh 0 (64K) | sKl 64K (64K) | sS 128K (66048) | sQh (1K) | sQl (1K)
//           sList 199168 (16 warps x 128 x float2 = 16K)   total 215552
#define ATTN_SMEM 215552

__global__ __launch_bounds__(512, 1)
void attn_kernel(float* __restrict__ attnw /* [16,1024,1024] */)
{
    extern __shared__ __align__(128) char smem[];
    char*  sKh = smem;
    char*  sKl = smem + 65536;
    float* sS  = reinterpret_cast<float*>(smem + 131072);   // 16 x 1032 f32
    char*  sQh = smem + 197120;
    char*  sQl = smem + 198144;
    float2* sList = reinterpret_cast<float2*>(smem + 199168);

    const int bh   = blockIdx.x;
    const int tid  = threadIdx.x;
    const int lane = tid & 31;
    const int wid  = tid >> 5;      // 0..15
    const int b    = bh >> 3;
    const int h    = bh & 7;

    const uint32_t skh = smem_u32(sKh), skl = smem_u32(sKl);
    const uint32_t sqh = smem_u32(sQh), sql = smem_u32(sQl);

    // ---- load K[bh] hi/lo into packed-swizzled smem ----
    for (int idx = tid; idx < 4096; idx += 512) {
        int s = idx >> 2, c = idx & 3;
        uint32_t off = swz64(s, c);
        size_t gb = (((size_t)bh << 10) + s) * 32 + c * 8;
        *reinterpret_cast<uint4*>(sKh + off) =
            *reinterpret_cast<const uint4*>(g_Kh + gb);
        *reinterpret_cast<uint4*>(sKl + off) =
            *reinterpret_cast<const uint4*>(g_Kl + gb);
    }
    __syncthreads();

    const float* Vbase = g_QKV + (size_t)(512 + h * 32) + (size_t)b * 768;
    const int brow = (lane & 7) + ((lane >> 4) << 3);
    const int bcs  = (lane >> 3) & 1;
    const int arow = lane & 15;
    const int acs  = lane >> 4;
    float2* Lst = sList + wid * 128;

    for (int wave = 0; wave < 64; wave++) {
        const int t0 = wave * 16;

        // ---- fill Q tile (16 rows x 32 bf16, hi+lo) ----
        if (tid < 128) {
            int a = tid >> 6, q = tid & 63;
            int r = q >> 2, c = q & 3;
            size_t gb = (((size_t)bh << 10) + t0 + r) * 32 + c * 8;
            const __nv_bfloat16* src = (a ? g_Ql : g_Qh) + gb;
            char* dst = (a ? sQl : sQh) + swz64(r, c);
            *reinterpret_cast<uint4*>(dst) = *reinterpret_cast<const uint4*>(src);
        }
        __syncthreads();   // Q ready; prev-wave sS reads complete

        // ---- MMA: warp wid covers score cols [wid*64, wid*64+64) ----
        uint32_t ah[2][4], al[2][4];
#pragma unroll
        for (int ks = 0; ks < 2; ks++) {
            uint32_t off = swz64(arow, 2 * ks + acs);
            ldmx4(ah[ks], sqh + off);
            ldmx4(al[ks], sql + off);
        }
        float d[8][4];
#pragma unroll
        for (int nt = 0; nt < 8; nt++)
#pragma unroll
            for (int j = 0; j < 4; j++) d[nt][j] = 0.f;

#pragma unroll
        for (int ks = 0; ks < 2; ks++) {
#pragma unroll
            for (int nt4 = 0; nt4 < 4; nt4++) {
                int srow = wid * 64 + nt4 * 16 + brow;
                uint32_t off = swz64(srow, 2 * ks + bcs);
                uint32_t bhf[4], blf[4];
                ldmx4(bhf, skh + off);
                ldmx4(blf, skl + off);
                mma_bf16(d[nt4 * 2 + 0], ah[ks], bhf[0], bhf[1]);
                mma_bf16(d[nt4 * 2 + 1], ah[ks], bhf[2], bhf[3]);
                mma_bf16(d[nt4 * 2 + 0], ah[ks], blf[0], blf[1]);
                mma_bf16(d[nt4 * 2 + 1], ah[ks], blf[2], blf[3]);
                mma_bf16(d[nt4 * 2 + 0], al[ks], bhf[0], bhf[1]);
                mma_bf16(d[nt4 * 2 + 1], al[ks], bhf[2], bhf[3]);
            }
        }

        // ---- scatter fragments to score buffer ----
        {
            int rr = lane >> 2;
            int cb = wid * 64 + 2 * (lane & 3);
#pragma unroll
            for (int nt = 0; nt < 8; nt++) {
                *reinterpret_cast<float2*>(&sS[rr * 1032 + cb + nt * 8]) =
                    make_float2(d[nt][0], d[nt][1]);
                *reinterpret_cast<float2*>(&sS[(rr + 8) * 1032 + cb + nt * 8]) =
                    make_float2(d[nt][2], d[nt][3]);
            }
        }
        __syncthreads();   // scores ready

        // ---- sparsemax + AV + avg attn weights: warp wid owns row t0+wid ----
        {
            float a[32];
#pragma unroll
            for (int c = 0; c < 8; c++) {
                float4 v4 = *reinterpret_cast<const float4*>(
                    &sS[wid * 1032 + c * 128 + lane * 4]);
                a[c * 4 + 0] = v4.x; a[c * 4 + 1] = v4.y;
                a[c * 4 + 2] = v4.z; a[c * 4 + 3] = v4.w;
            }

            // Michelot from tau = max(z) - 1 (valid support superset)
            float mx = a[0];
#pragma unroll
            for (int i = 1; i < 32; i++) mx = fmaxf(mx, a[i]);
#pragma unroll
            for (int o = 16; o > 0; o >>= 1)
                mx = fmaxf(mx, __shfl_xor_sync(0xffffffffu, mx, o));
            float tau = mx - 1.0f;
            int prevc = -1;

            for (int iter = 0; iter < 64; iter++) {
                float s = 0.f;
                int   c = 0;
#pragma unroll
                for (int i = 0; i < 32; i++) {
                    if (a[i] > tau) { s += a[i]; c++; }
                }
#pragma unroll
                for (int o = 16; o > 0; o >>= 1) {
                    s += __shfl_xor_sync(0xffffffffu, s, o);
                    c += __shfl_xor_sync(0xffffffffu, c, o);
                }
                if (c == prevc) break;
                tau = (s - 1.0f) / (float)c;
                prevc = c;
            }

            const int t = t0 + wid;
            float* awrow = attnw + ((size_t)b * TLEN + t) * SLEN;
            float ov0 = 0.f, ov1 = 0.f, ov2 = 0.f, ov3 = 0.f;

            // 8 chunks of 128 s-positions: compact actives, then 4-way-ILP AV
#pragma unroll 1
            for (int ch = 0; ch < 8; ch++) {
                int cnt = 0;
#pragma unroll
                for (int j = 0; j < 4; j++) {
                    float v = a[ch * 4 + j];
                    bool act = v > tau;
                    unsigned m = __ballot_sync(0xffffffffu, act);
                    if (act) {
                        float w = v - tau;
                        int s = ch * 128 + lane * 4 + j;
                        int pos = cnt + __popc(m & ((1u << lane) - 1u));
                        Lst[pos] = make_float2(w, __int_as_float(s));
                        atomicAdd(awrow + s, 0.125f * w);
                    }
                    cnt += __popc(m);
                }
                __syncwarp();
                int p = 0;
                for (; p + 4 <= cnt; p += 4) {
                    float2 e0 = Lst[p + 0], e1 = Lst[p + 1];
                    float2 e2 = Lst[p + 2], e3 = Lst[p + 3];
                    float v0 = Vbase[(size_t)__float_as_int(e0.y) * 12288 + lane];
                    float v1 = Vbase[(size_t)__float_as_int(e1.y) * 12288 + lane];
                    float v2 = Vbase[(size_t)__float_as_int(e2.y) * 12288 + lane];
                    float v3 = Vbase[(size_t)__float_as_int(e3.y) * 12288 + lane];
                    ov0 = fmaf(e0.x, v0, ov0);
                    ov1 = fmaf(e1.x, v1, ov1);
                    ov2 = fmaf(e2.x, v2, ov2);
                    ov3 = fmaf(e3.x, v3, ov3);
                }
                for (; p < cnt; p++) {
                    float2 e = Lst[p];
                    ov0 = fmaf(e.x, Vbase[(size_t)__float_as_int(e.y) * 12288 + lane], ov0);
                }
                __syncwarp();
            }
            float outv = (ov0 + ov1) + (ov2 + ov3);
            g_ctx[((size_t)t * BSZ + b) * EMB + h * HD + lane] = outv;
        }
    }
}

// ---------------- launcher ---------------------------------------------------
extern "C" void kernel_launch(void* const* d_in, const int* in_sizes, int n_in,
                              void* d_out, int out_size)
{
    const float* query = (const float*)d_in[0];
    const float* key   = (const float*)d_in[1];
    const float* value = (const float*)d_in[2];
    const float* Win   = (const float*)d_in[3];
    const float* bin   = (const float*)d_in[4];
    const float* Wout  = (const float*)d_in[5];
    const float* bout  = (const float*)d_in[6];

    float* outp  = (float*)d_out;                         // [1024,16,256]
    float* attnw = outp + (size_t)MROWS * EMB;            // [16,1024,1024]

    cudaFuncSetAttribute(attn_kernel, cudaFuncAttributeMaxDynamicSharedMemorySize,
                         ATTN_SMEM);
    cudaFuncSetAttribute(gemm_mma<0>, cudaFuncAttributeMaxDynamicSharedMemorySize,
                         GM_SMEM);
    cudaFuncSetAttribute(gemm_mma<1>, cudaFuncAttributeMaxDynamicSharedMemorySize,
                         GM_SMEM);

    // 1) zero averaged attention-weights output (sparse atomics accumulate into it)
    zero_f4<<<2048, 256>>>((float4*)attnw, (int)((size_t)BSZ * TLEN * SLEN / 4));

    // 2) QKV projection (M=16384, N=768, K=256) + bf16 hi/lo emit for Q,K
    gemm_mma<0><<<dim3(6, MROWS / 128), 256, GM_SMEM>>>(query, key, value, Win, bin, nullptr);

    // 3) fused attention: HMMA scores + sparsemax + compacted AV + avg weights
    attn_kernel<<<BH, 512, ATTN_SMEM>>>(attnw);

    // 4) output projection (M=16384, N=256, K=256)
    gemm_mma<1><<<dim3(2, MROWS / 128), 256, GM_SMEM>>>(nullptr, nullptr, nullptr, Wout, bout, outp);
}

// round 13
// speedup vs baseline: 1.0099x; 1.0099x over previous
#include <cuda_runtime.h>
#include <cuda_bf16.h>
#include <cstdint>

// Problem constants
#define TLEN   1024
#define SLEN   1024
#define BSZ    16
#define EMB    256
#define NH     8
#define HD     32
#define BH     (BSZ*NH)        // 128
#define MROWS  (TLEN*BSZ)      // 16384
#define QSCALE 0.17677669529663688f   // 1/sqrt(32)

typedef unsigned long long u64;

__device__ __forceinline__ uint32_t smem_u32(const void* p) {
    uint32_t a;
    asm("{ .reg .u64 t; cvta.to.shared.u64 t, %1; cvt.u32.u64 %0, t; }"
        : "=r"(a) : "l"(p));
    return a;
}

// ---- mma.sync helpers (base ISA; sm_103 target has no tcgen05) --------------
__device__ __forceinline__ void ldmx4(uint32_t r[4], uint32_t addr) {
    asm volatile("ldmatrix.sync.aligned.m8n8.x4.shared.b16 {%0,%1,%2,%3}, [%4];"
                 : "=r"(r[0]), "=r"(r[1]), "=r"(r[2]), "=r"(r[3]) : "r"(addr));
}
__device__ __forceinline__ void mma_bf16(float d[4], const uint32_t a[4],
                                         uint32_t b0, uint32_t b1) {
    asm volatile(
        "mma.sync.aligned.m16n8k16.row.col.f32.bf16.bf16.f32 "
        "{%0,%1,%2,%3}, {%4,%5,%6,%7}, {%8,%9}, {%0,%1,%2,%3};"
        : "+f"(d[0]), "+f"(d[1]), "+f"(d[2]), "+f"(d[3])
        : "r"(a[0]), "r"(a[1]), "r"(a[2]), "r"(a[3]), "r"(b0), "r"(b1));
}

// ---------------- scratch (device globals; no allocation allowed) ----------
__device__ float g_QKV[(size_t)MROWS * 768];   // [t*16+b][sec*256+h*32+d], q pre-scaled
__device__ float g_ctx[(size_t)MROWS * EMB];   // [t*16+b][h*32+d]
// bf16 hi/lo splits of Q (scaled) and K, per-bh contiguous: [bh][t or s][32]
__device__ __align__(16) __nv_bfloat16 g_Qh[(size_t)BH*1024*32];
__device__ __align__(16) __nv_bfloat16 g_Ql[(size_t)BH*1024*32];
__device__ __align__(16) __nv_bfloat16 g_Kh[(size_t)BH*1024*32];
__device__ __align__(16) __nv_bfloat16 g_Kl[(size_t)BH*1024*32];

// ---------------- zero kernel ----------------------------------------------
__global__ void zero_f4(float4* __restrict__ p, int n4) {
    int i = blockIdx.x * blockDim.x + threadIdx.x;
    int stride = gridDim.x * blockDim.x;
    float4 z = make_float4(0.f, 0.f, 0.f, 0.f);
    for (; i < n4; i += stride) p[i] = z;
}

// ---------------- bf16-split HMMA GEMM:  out = X.W^T + b --------------------
#define GM_SMEM 65536

__device__ __forceinline__ void conv_store_g(float4 x, char* hi, char* lo,
                                             int row, int kg4) {
    __nv_bfloat162 h01 = __floats2bfloat162_rn(x.x, x.y);
    __nv_bfloat162 h23 = __floats2bfloat162_rn(x.z, x.w);
    float r0 = x.x - __bfloat162float(h01.x);
    float r1 = x.y - __bfloat162float(h01.y);
    float r2 = x.z - __bfloat162float(h23.x);
    float r3 = x.w - __bfloat162float(h23.y);
    __nv_bfloat162 l01 = __floats2bfloat162_rn(r0, r1);
    __nv_bfloat162 l23 = __floats2bfloat162_rn(r2, r3);
    int c  = kg4 >> 3;
    int sw = row * 128 + ((c ^ (row & 7)) << 4) + ((kg4 & 7) * 2);
    u64 hp = (u64)(*reinterpret_cast<uint32_t*>(&h01)) |
             ((u64)(*reinterpret_cast<uint32_t*>(&h23)) << 32);
    u64 lp = (u64)(*reinterpret_cast<uint32_t*>(&l01)) |
             ((u64)(*reinterpret_cast<uint32_t*>(&l23)) << 32);
    *reinterpret_cast<u64*>(hi + sw) = hp;
    *reinterpret_cast<u64*>(lo + sw) = lp;
}

template<int MODE>
__global__ __launch_bounds__(256)
void gemm_mma(const float* __restrict__ Xq, const float* __restrict__ Xk,
              const float* __restrict__ Xv, const float* __restrict__ W,
              const float* __restrict__ bias, float* __restrict__ outp)
{
    extern __shared__ __align__(128) char smem[];
    char* Ah = smem;
    char* Al = smem + 16384;
    char* Bh = smem + 32768;
    char* Bl = smem + 49152;

    const int tid  = threadIdx.x;
    const int lane = tid & 31;
    const int wid  = tid >> 5;
    const int mw   = (wid & 3) * 32;
    const int nw   = (wid >> 2) * 64;
    const int n0 = blockIdx.x * 128;
    const int m0 = blockIdx.y * 128;

    const float* X;
    if (MODE == 0) {
        int sec = n0 >> 8;
        X = (sec == 0) ? Xq : (sec == 1 ? Xk : Xv);
    } else {
        X = g_ctx;
    }

    const uint32_t sA = smem_u32(Ah), sAl = smem_u32(Al);
    const uint32_t sB = smem_u32(Bh), sBl = smem_u32(Bl);

    float d[2][8][4];
#pragma unroll
    for (int mt = 0; mt < 2; mt++)
#pragma unroll
        for (int nt = 0; nt < 8; nt++)
#pragma unroll
            for (int j = 0; j < 4; j++) d[mt][nt][j] = 0.f;

    const int arow = lane & 15;
    const int acs  = lane >> 4;
    const int brow = (lane & 7) + ((lane >> 4) << 3);
    const int bcs  = (lane >> 3) & 1;
    const int lxor = lane & 7;

    for (int kc = 0; kc < 4; kc++) {
#pragma unroll
        for (int g = tid, it = 0; it < 8; g += 256, it++) {
            int row = g >> 4;
            int kg4 = (g & 15) * 4;
            float4 xa = *reinterpret_cast<const float4*>(
                X + (size_t)(m0 + row) * 256 + kc * 64 + kg4);
            conv_store_g(xa, Ah, Al, row, kg4);
            float4 xb = *reinterpret_cast<const float4*>(
                W + (size_t)(n0 + row) * 256 + kc * 64 + kg4);
            conv_store_g(xb, Bh, Bl, row, kg4);
        }
        __syncthreads();

#pragma unroll
        for (int ks = 0; ks < 4; ks++) {
            uint32_t ah[2][4], al[2][4], bh[4][4], bl[4][4];
#pragma unroll
            for (int mt = 0; mt < 2; mt++) {
                int row = mw + mt * 16 + arow;
                uint32_t off = (uint32_t)(row * 128 + (((2 * ks + acs) ^ lxor) << 4));
                ldmx4(ah[mt], sA + off);
                ldmx4(al[mt], sAl + off);
            }
#pragma unroll
            for (int nt4 = 0; nt4 < 4; nt4++) {
                int row = nw + nt4 * 16 + brow;
                uint32_t off = (uint32_t)(row * 128 + (((2 * ks + bcs) ^ lxor) << 4));
                ldmx4(bh[nt4], sB + off);
                ldmx4(bl[nt4], sBl + off);
            }
#pragma unroll
            for (int mt = 0; mt < 2; mt++)
#pragma unroll
                for (int nt4 = 0; nt4 < 4; nt4++) {
                    mma_bf16(d[mt][nt4 * 2 + 0], ah[mt], bh[nt4][0], bh[nt4][1]);
                    mma_bf16(d[mt][nt4 * 2 + 1], ah[mt], bh[nt4][2], bh[nt4][3]);
                    mma_bf16(d[mt][nt4 * 2 + 0], ah[mt], bl[nt4][0], bl[nt4][1]);
                    mma_bf16(d[mt][nt4 * 2 + 1], ah[mt], bl[nt4][2], bl[nt4][3]);
                    mma_bf16(d[mt][nt4 * 2 + 0], al[mt], bh[nt4][0], bh[nt4][1]);
                    mma_bf16(d[mt][nt4 * 2 + 1], al[mt], bh[nt4][2], bh[nt4][3]);
                }
        }
        __syncthreads();
    }

    // ---- epilogue ----
    const float scl = (MODE == 0 && n0 < 256) ? QSCALE : 1.0f;
    const int qrow = lane >> 2;
    const int qcol = (lane & 3) * 2;
#pragma unroll
    for (int mt = 0; mt < 2; mt++) {
#pragma unroll
        for (int nt = 0; nt < 8; nt++) {
            int n = n0 + nw + nt * 8 + qcol;
            float2 bv = *reinterpret_cast<const float2*>(bias + n);
            int r0 = m0 + mw + mt * 16 + qrow;
#pragma unroll
            for (int hfl = 0; hfl < 2; hfl++) {
                int r = r0 + hfl * 8;
                float2 v;
                v.x = (d[mt][nt][hfl * 2 + 0] + bv.x) * scl;
                v.y = (d[mt][nt][hfl * 2 + 1] + bv.y) * scl;
                float* dst = (MODE == 0) ? (g_QKV + (size_t)r * 768 + n)
                                         : (outp  + (size_t)r * 256 + n);
                *reinterpret_cast<float2*>(dst) = v;
                if (MODE == 0) {
                    int sec = n >> 8;
                    if (sec < 2) {
                        int hh = (n >> 5) & 7, dd = n & 31;
                        int tt = r >> 4,      bb = r & 15;
                        size_t base = (((size_t)(bb * 8 + hh) << 10) + tt) * 32 + dd;
                        __nv_bfloat162 hi2 = __floats2bfloat162_rn(v.x, v.y);
                        float rx = v.x - __bfloat162float(hi2.x);
                        float ry = v.y - __bfloat162float(hi2.y);
                        __nv_bfloat162 lo2 = __floats2bfloat162_rn(rx, ry);
                        if (sec == 0) {
                            *reinterpret_cast<__nv_bfloat162*>(g_Qh + base) = hi2;
                            *reinterpret_cast<__nv_bfloat162*>(g_Ql + base) = lo2;
                        } else {
                            *reinterpret_cast<__nv_bfloat162*>(g_Kh + base) = hi2;
                            *reinterpret_cast<__nv_bfloat162*>(g_Kl + base) = lo2;
                        }
                    }
                }
            }
        }
    }
}

// ---------------- fused attention v4: HMMA scores + 4-way interleaved AV ----
// 128 blocks (one per bh), 512 threads (16 warps).
// K hi/lo resident in smem (2 s-rows packed per 128B row, XOR swizzle).
// 64 waves of 16 t-rows: MMA phase fills 16x1024 score buffer; epilogue:
// warp w owns row w -> Michelot sparsemax, then AV with 4 masks drained in
// lockstep (register-only 4-way ILP on the V loads; no smem, no syncwarp).
__device__ __forceinline__ uint32_t swz64(int s, int c) {
    int p = s >> 1;
    int j = (((s & 1) << 2) | c) ^ (p & 7);
    return (uint32_t)(p * 128 + j * 16);
}

#define ATTN_SMEM (65536 + 65536 + 66048 + 1024 + 1024)

__global__ __launch_bounds__(512, 1)
void attn_kernel(float* __restrict__ attnw /* [16,1024,1024] */)
{
    extern __shared__ __align__(128) char smem[];
    char*  sKh = smem;                                   // 64KB
    char*  sKl = smem + 65536;                           // 64KB
    float* sS  = reinterpret_cast<float*>(smem + 131072); // 16 x 1032 f32
    char*  sQh = smem + 131072 + 66048;                  // 1KB
    char*  sQl = sQh + 1024;                             // 1KB

    const int bh   = blockIdx.x;
    const int tid  = threadIdx.x;
    const int lane = tid & 31;
    const int wid  = tid >> 5;      // 0..15
    const int b    = bh >> 3;
    const int h    = bh & 7;

    const uint32_t skh = smem_u32(sKh), skl = smem_u32(sKl);
    const uint32_t sqh = smem_u32(sQh), sql = smem_u32(sQl);

    // ---- load K[bh] hi/lo into packed-swizzled smem ----
    for (int idx = tid; idx < 4096; idx += 512) {
        int s = idx >> 2, c = idx & 3;
        uint32_t off = swz64(s, c);
        size_t gb = (((size_t)bh << 10) + s) * 32 + c * 8;
        *reinterpret_cast<uint4*>(sKh + off) =
            *reinterpret_cast<const uint4*>(g_Kh + gb);
        *reinterpret_cast<uint4*>(sKl + off) =
            *reinterpret_cast<const uint4*>(g_Kl + gb);
    }
    __syncthreads();

    const float* Vbase = g_QKV + (size_t)(512 + h * 32) + (size_t)b * 768;
    const int brow = (lane & 7) + ((lane >> 4) << 3);
    const int bcs  = (lane >> 3) & 1;
    const int arow = lane & 15;
    const int acs  = lane >> 4;

    for (int wave = 0; wave < 64; wave++) {
        const int t0 = wave * 16;

        // ---- fill Q tile (16 rows x 32 bf16, hi+lo) ----
        if (tid < 128) {
            int a = tid >> 6, q = tid & 63;
            int r = q >> 2, c = q & 3;
            size_t gb = (((size_t)bh << 10) + t0 + r) * 32 + c * 8;
            const __nv_bfloat16* src = (a ? g_Ql : g_Qh) + gb;
            char* dst = (a ? sQl : sQh) + swz64(r, c);
            *reinterpret_cast<uint4*>(dst) = *reinterpret_cast<const uint4*>(src);
        }
        __syncthreads();   // Q ready; prev-wave sS reads complete

        // ---- MMA: warp wid covers score cols [wid*64, wid*64+64) ----
        uint32_t ah[2][4], al[2][4];
#pragma unroll
        for (int ks = 0; ks < 2; ks++) {
            uint32_t off = swz64(arow, 2 * ks + acs);
            ldmx4(ah[ks], sqh + off);
            ldmx4(al[ks], sql + off);
        }
        float d[8][4];
#pragma unroll
        for (int nt = 0; nt < 8; nt++)
#pragma unroll
            for (int j = 0; j < 4; j++) d[nt][j] = 0.f;

#pragma unroll
        for (int ks = 0; ks < 2; ks++) {
#pragma unroll
            for (int nt4 = 0; nt4 < 4; nt4++) {
                int srow = wid * 64 + nt4 * 16 + brow;
                uint32_t off = swz64(srow, 2 * ks + bcs);
                uint32_t bhf[4], blf[4];
                ldmx4(bhf, skh + off);
                ldmx4(blf, skl + off);
                mma_bf16(d[nt4 * 2 + 0], ah[ks], bhf[0], bhf[1]);
                mma_bf16(d[nt4 * 2 + 1], ah[ks], bhf[2], bhf[3]);
                mma_bf16(d[nt4 * 2 + 0], ah[ks], blf[0], blf[1]);
                mma_bf16(d[nt4 * 2 + 1], ah[ks], blf[2], blf[3]);
                mma_bf16(d[nt4 * 2 + 0], al[ks], bhf[0], bhf[1]);
                mma_bf16(d[nt4 * 2 + 1], al[ks], bhf[2], bhf[3]);
            }
        }

        // ---- scatter fragments to score buffer ----
        {
            int rr = lane >> 2;
            int cb = wid * 64 + 2 * (lane & 3);
#pragma unroll
            for (int nt = 0; nt < 8; nt++) {
                *reinterpret_cast<float2*>(&sS[rr * 1032 + cb + nt * 8]) =
                    make_float2(d[nt][0], d[nt][1]);
                *reinterpret_cast<float2*>(&sS[(rr + 8) * 1032 + cb + nt * 8]) =
                    make_float2(d[nt][2], d[nt][3]);
            }
        }
        __syncthreads();   // scores ready

        // ---- sparsemax + AV + avg attn weights: warp wid owns row t0+wid ----
        {
            float a[32];
#pragma unroll
            for (int c = 0; c < 8; c++) {
                float4 v4 = *reinterpret_cast<const float4*>(
                    &sS[wid * 1032 + c * 128 + lane * 4]);
                a[c * 4 + 0] = v4.x; a[c * 4 + 1] = v4.y;
                a[c * 4 + 2] = v4.z; a[c * 4 + 3] = v4.w;
            }

            // Michelot from tau = max(z) - 1 (valid support superset)
            float mx = a[0];
#pragma unroll
            for (int i = 1; i < 32; i++) mx = fmaxf(mx, a[i]);
#pragma unroll
            for (int o = 16; o > 0; o >>= 1)
                mx = fmaxf(mx, __shfl_xor_sync(0xffffffffu, mx, o));
            float tau = mx - 1.0f;
            int prevc = -1;

            for (int iter = 0; iter < 64; iter++) {
                float s = 0.f;
                int   c = 0;
#pragma unroll
                for (int i = 0; i < 32; i++) {
                    if (a[i] > tau) { s += a[i]; c++; }
                }
#pragma unroll
                for (int o = 16; o > 0; o >>= 1) {
                    s += __shfl_xor_sync(0xffffffffu, s, o);
                    c += __shfl_xor_sync(0xffffffffu, c, o);
                }
                if (c == prevc) break;
                tau = (s - 1.0f) / (float)c;
                prevc = c;
            }

            const int t = t0 + wid;
            float* awrow = attnw + ((size_t)b * TLEN + t) * SLEN;
            float ov0 = 0.f, ov1 = 0.f, ov2 = 0.f, ov3 = 0.f;

            // 8 chunks of 128 s: drain 4 masks in lockstep (4-way LDG ILP)
#pragma unroll 1
            for (int ch = 0; ch < 8; ch++) {
                float w0 = a[ch * 4 + 0] - tau;
                float w1 = a[ch * 4 + 1] - tau;
                float w2 = a[ch * 4 + 2] - tau;
                float w3 = a[ch * 4 + 3] - tau;
                unsigned m0 = __ballot_sync(0xffffffffu, w0 > 0.f);
                unsigned m1 = __ballot_sync(0xffffffffu, w1 > 0.f);
                unsigned m2 = __ballot_sync(0xffffffffu, w2 > 0.f);
                unsigned m3 = __ballot_sync(0xffffffffu, w3 > 0.f);
                int sb = ch * 128 + lane * 4;
                if (w0 > 0.f) atomicAdd(awrow + sb + 0, 0.125f * w0);
                if (w1 > 0.f) atomicAdd(awrow + sb + 1, 0.125f * w1);
                if (w2 > 0.f) atomicAdd(awrow + sb + 2, 0.125f * w2);
                if (w3 > 0.f) atomicAdd(awrow + sb + 3, 0.125f * w3);

                const float* Vc = Vbase + (size_t)(ch * 128) * 12288 + lane;
                while (m0 | m1 | m2 | m3) {
                    if (m0) {
                        int l = __ffs(m0) - 1; m0 &= m0 - 1;
                        float wj = __shfl_sync(0xffffffffu, w0, l);
                        ov0 = fmaf(wj, Vc[(size_t)(l * 4 + 0) * 12288], ov0);
                    }
                    if (m1) {
                        int l = __ffs(m1) - 1; m1 &= m1 - 1;
                        float wj = __shfl_sync(0xffffffffu, w1, l);
                        ov1 = fmaf(wj, Vc[(size_t)(l * 4 + 1) * 12288], ov1);
                    }
                    if (m2) {
                        int l = __ffs(m2) - 1; m2 &= m2 - 1;
                        float wj = __shfl_sync(0xffffffffu, w2, l);
                        ov2 = fmaf(wj, Vc[(size_t)(l * 4 + 2) * 12288], ov2);
                    }
                    if (m3) {
                        int l = __ffs(m3) - 1; m3 &= m3 - 1;
                        float wj = __shfl_sync(0xffffffffu, w3, l);
                        ov3 = fmaf(wj, Vc[(size_t)(l * 4 + 3) * 12288], ov3);
                    }
                }
            }
            float outv = (ov0 + ov1) + (ov2 + ov3);
            g_ctx[((size_t)t * BSZ + b) * EMB + h * HD + lane] = outv;
        }
    }
}

// ---------------- launcher ---------------------------------------------------
extern "C" void kernel_launch(void* const* d_in, const int* in_sizes, int n_in,
                              void* d_out, int out_size)
{
    const float* query = (const float*)d_in[0];
    const float* key   = (const float*)d_in[1];
    const float* value = (const float*)d_in[2];
    const float* Win   = (const float*)d_in[3];
    const float* bin   = (const float*)d_in[4];
    const float* Wout  = (const float*)d_in[5];
    const float* bout  = (const float*)d_in[6];

    float* outp  = (float*)d_out;                         // [1024,16,256]
    float* attnw = outp + (size_t)MROWS * EMB;            // [16,1024,1024]

    cudaFuncSetAttribute(attn_kernel, cudaFuncAttributeMaxDynamicSharedMemorySize,
                         ATTN_SMEM);
    cudaFuncSetAttribute(gemm_mma<0>, cudaFuncAttributeMaxDynamicSharedMemorySize,
                         GM_SMEM);
    cudaFuncSetAttribute(gemm_mma<1>, cudaFuncAttributeMaxDynamicSharedMemorySize,
                         GM_SMEM);

    // 1) zero averaged attention-weights output (sparse atomics accumulate into it)
    zero_f4<<<2048, 256>>>((float4*)attnw, (int)((size_t)BSZ * TLEN * SLEN / 4));

    // 2) QKV projection (M=16384, N=768, K=256) + bf16 hi/lo emit for Q,K
    gemm_mma<0><<<dim3(6, MROWS / 128), 256, GM_SMEM>>>(query, key, value, Win, bin, nullptr);

    // 3) fused attention: HMMA scores + sparsemax + interleaved AV + weights
    attn_kernel<<<BH, 512, ATTN_SMEM>>>(attnw);

    // 4) output projection (M=16384, N=256, K=256)
    gemm_mma<1><<<dim3(2, MROWS / 128), 256, GM_SMEM>>>(nullptr, nullptr, nullptr, Wout, bout, outp);
}

// round 14
// speedup vs baseline: 1.3835x; 1.3700x over previous
#include <cuda_runtime.h>
#include <cuda_bf16.h>
#include <cstdint>

// Problem constants
#define TLEN   1024
#define SLEN   1024
#define BSZ    16
#define EMB    256
#define NH     8
#define HD     32
#define BH     (BSZ*NH)        // 128
#define MROWS  (TLEN*BSZ)      // 16384
#define QSCALE 0.17677669529663688f   // 1/sqrt(32)
#define NBLK   148             // persistent attn grid (one CTA per SM)

typedef unsigned long long u64;

__device__ __forceinline__ uint32_t smem_u32(const void* p) {
    uint32_t a;
    asm("{ .reg .u64 t; cvta.to.shared.u64 t, %1; cvt.u32.u64 %0, t; }"
        : "=r"(a) : "l"(p));
    return a;
}

// ---- mma.sync helpers (base ISA; sm_103 target has no tcgen05) --------------
__device__ __forceinline__ void ldmx4(uint32_t r[4], uint32_t addr) {
    asm volatile("ldmatrix.sync.aligned.m8n8.x4.shared.b16 {%0,%1,%2,%3}, [%4];"
                 : "=r"(r[0]), "=r"(r[1]), "=r"(r[2]), "=r"(r[3]) : "r"(addr));
}
__device__ __forceinline__ void mma_bf16(float d[4], const uint32_t a[4],
                                         uint32_t b0, uint32_t b1) {
    asm volatile(
        "mma.sync.aligned.m16n8k16.row.col.f32.bf16.bf16.f32 "
        "{%0,%1,%2,%3}, {%4,%5,%6,%7}, {%8,%9}, {%0,%1,%2,%3};"
        : "+f"(d[0]), "+f"(d[1]), "+f"(d[2]), "+f"(d[3])
        : "r"(a[0]), "r"(a[1]), "r"(a[2]), "r"(a[3]), "r"(b0), "r"(b1));
}

// ---------------- scratch (device globals; no allocation allowed) ----------
__device__ float g_QKV[(size_t)MROWS * 768];   // [t*16+b][sec*256+h*32+d], q pre-scaled
__device__ float g_ctx[(size_t)MROWS * EMB];   // [t*16+b][h*32+d]
// bf16 hi/lo splits of Q (scaled) and K, per-bh contiguous: [bh][t or s][32]
__device__ __align__(16) __nv_bfloat16 g_Qh[(size_t)BH*1024*32];
__device__ __align__(16) __nv_bfloat16 g_Ql[(size_t)BH*1024*32];
__device__ __align__(16) __nv_bfloat16 g_Kh[(size_t)BH*1024*32];
__device__ __align__(16) __nv_bfloat16 g_Kl[(size_t)BH*1024*32];

// ---------------- zero kernel ----------------------------------------------
__global__ void zero_f4(float4* __restrict__ p, int n4) {
    int i = blockIdx.x * blockDim.x + threadIdx.x;
    int stride = gridDim.x * blockDim.x;
    float4 z = make_float4(0.f, 0.f, 0.f, 0.f);
    for (; i < n4; i += stride) p[i] = z;
}

// ---------------- bf16-split HMMA GEMM:  out = X.W^T + b --------------------
#define GM_SMEM 65536

__device__ __forceinline__ void conv_store_g(float4 x, char* hi, char* lo,
                                             int row, int kg4) {
    __nv_bfloat162 h01 = __floats2bfloat162_rn(x.x, x.y);
    __nv_bfloat162 h23 = __floats2bfloat162_rn(x.z, x.w);
    float r0 = x.x - __bfloat162float(h01.x);
    float r1 = x.y - __bfloat162float(h01.y);
    float r2 = x.z - __bfloat162float(h23.x);
    float r3 = x.w - __bfloat162float(h23.y);
    __nv_bfloat162 l01 = __floats2bfloat162_rn(r0, r1);
    __nv_bfloat162 l23 = __floats2bfloat162_rn(r2, r3);
    int c  = kg4 >> 3;
    int sw = row * 128 + ((c ^ (row & 7)) << 4) + ((kg4 & 7) * 2);
    u64 hp = (u64)(*reinterpret_cast<uint32_t*>(&h01)) |
             ((u64)(*reinterpret_cast<uint32_t*>(&h23)) << 32);
    u64 lp = (u64)(*reinterpret_cast<uint32_t*>(&l01)) |
             ((u64)(*reinterpret_cast<uint32_t*>(&l23)) << 32);
    *reinterpret_cast<u64*>(hi + sw) = hp;
    *reinterpret_cast<u64*>(lo + sw) = lp;
}

template<int MODE>
__global__ __launch_bounds__(256)
void gemm_mma(const float* __restrict__ Xq, const float* __restrict__ Xk,
              const float* __restrict__ Xv, const float* __restrict__ W,
              const float* __restrict__ bias, float* __restrict__ outp)
{
    extern __shared__ __align__(128) char smem[];
    char* Ah = smem;
    char* Al = smem + 16384;
    char* Bh = smem + 32768;
    char* Bl = smem + 49152;

    const int tid  = threadIdx.x;
    const int lane = tid & 31;
    const int wid  = tid >> 5;
    const int mw   = (wid & 3) * 32;
    const int nw   = (wid >> 2) * 64;
    const int n0 = blockIdx.x * 128;
    const int m0 = blockIdx.y * 128;

    const float* X;
    if (MODE == 0) {
        int sec = n0 >> 8;
        X = (sec == 0) ? Xq : (sec == 1 ? Xk : Xv);
    } else {
        X = g_ctx;
    }

    const uint32_t sA = smem_u32(Ah), sAl = smem_u32(Al);
    const uint32_t sB = smem_u32(Bh), sBl = smem_u32(Bl);

    float d[2][8][4];
#pragma unroll
    for (int mt = 0; mt < 2; mt++)
#pragma unroll
        for (int nt = 0; nt < 8; nt++)
#pragma unroll
            for (int j = 0; j < 4; j++) d[mt][nt][j] = 0.f;

    const int arow = lane & 15;
    const int acs  = lane >> 4;
    const int brow = (lane & 7) + ((lane >> 4) << 3);
    const int bcs  = (lane >> 3) & 1;
    const int lxor = lane & 7;

    for (int kc = 0; kc < 4; kc++) {
#pragma unroll
        for (int g = tid, it = 0; it < 8; g += 256, it++) {
            int row = g >> 4;
            int kg4 = (g & 15) * 4;
            float4 xa = *reinterpret_cast<const float4*>(
                X + (size_t)(m0 + row) * 256 + kc * 64 + kg4);
            conv_store_g(xa, Ah, Al, row, kg4);
            float4 xb = *reinterpret_cast<const float4*>(
                W + (size_t)(n0 + row) * 256 + kc * 64 + kg4);
            conv_store_g(xb, Bh, Bl, row, kg4);
        }
        __syncthreads();

#pragma unroll
        for (int ks = 0; ks < 4; ks++) {
            uint32_t ah[2][4], al[2][4], bh[4][4], bl[4][4];
#pragma unroll
            for (int mt = 0; mt < 2; mt++) {
                int row = mw + mt * 16 + arow;
                uint32_t off = (uint32_t)(row * 128 + (((2 * ks + acs) ^ lxor) << 4));
                ldmx4(ah[mt], sA + off);
                ldmx4(al[mt], sAl + off);
            }
#pragma unroll
            for (int nt4 = 0; nt4 < 4; nt4++) {
                int row = nw + nt4 * 16 + brow;
                uint32_t off = (uint32_t)(row * 128 + (((2 * ks + bcs) ^ lxor) << 4));
                ldmx4(bh[nt4], sB + off);
                ldmx4(bl[nt4], sBl + off);
            }
#pragma unroll
            for (int mt = 0; mt < 2; mt++)
#pragma unroll
                for (int nt4 = 0; nt4 < 4; nt4++) {
                    mma_bf16(d[mt][nt4 * 2 + 0], ah[mt], bh[nt4][0], bh[nt4][1]);
                    mma_bf16(d[mt][nt4 * 2 + 1], ah[mt], bh[nt4][2], bh[nt4][3]);
                    mma_bf16(d[mt][nt4 * 2 + 0], ah[mt], bl[nt4][0], bl[nt4][1]);
                    mma_bf16(d[mt][nt4 * 2 + 1], ah[mt], bl[nt4][2], bl[nt4][3]);
                    mma_bf16(d[mt][nt4 * 2 + 0], al[mt], bh[nt4][0], bh[nt4][1]);
                    mma_bf16(d[mt][nt4 * 2 + 1], al[mt], bh[nt4][2], bh[nt4][3]);
                }
        }
        __syncthreads();
    }

    // ---- epilogue ----
    const float scl = (MODE == 0 && n0 < 256) ? QSCALE : 1.0f;
    const int qrow = lane >> 2;
    const int qcol = (lane & 3) * 2;
#pragma unroll
    for (int mt = 0; mt < 2; mt++) {
#pragma unroll
        for (int nt = 0; nt < 8; nt++) {
            int n = n0 + nw + nt * 8 + qcol;
            float2 bv = *reinterpret_cast<const float2*>(bias + n);
            int r0 = m0 + mw + mt * 16 + qrow;
#pragma unroll
            for (int hfl = 0; hfl < 2; hfl++) {
                int r = r0 + hfl * 8;
                float2 v;
                v.x = (d[mt][nt][hfl * 2 + 0] + bv.x) * scl;
                v.y = (d[mt][nt][hfl * 2 + 1] + bv.y) * scl;
                float* dst = (MODE == 0) ? (g_QKV + (size_t)r * 768 + n)
                                         : (outp  + (size_t)r * 256 + n);
                *reinterpret_cast<float2*>(dst) = v;
                if (MODE == 0) {
                    int sec = n >> 8;
                    if (sec < 2) {
                        int hh = (n >> 5) & 7, dd = n & 31;
                        int tt = r >> 4,      bb = r & 15;
                        size_t base = (((size_t)(bb * 8 + hh) << 10) + tt) * 32 + dd;
                        __nv_bfloat162 hi2 = __floats2bfloat162_rn(v.x, v.y);
                        float rx = v.x - __bfloat162float(hi2.x);
                        float ry = v.y - __bfloat162float(hi2.y);
                        __nv_bfloat162 lo2 = __floats2bfloat162_rn(rx, ry);
                        if (sec == 0) {
                            *reinterpret_cast<__nv_bfloat162*>(g_Qh + base) = hi2;
                            *reinterpret_cast<__nv_bfloat162*>(g_Ql + base) = lo2;
                        } else {
                            *reinterpret_cast<__nv_bfloat162*>(g_Kh + base) = hi2;
                            *reinterpret_cast<__nv_bfloat162*>(g_Kl + base) = lo2;
                        }
                    }
                }
            }
        }
    }
}

// ---------------- fused attention v5: persistent balanced work units --------
// 148 persistent blocks, 512 threads (16 warps). Work unit = (bh, wave of 16
// t-rows); 8192 units split contiguously (bh-major) so each block reloads K
// at most twice. Per unit: HMMA scores -> 16x1024 smem buffer; warp w owns
// row w: Michelot sparsemax + AV + avg-attn-weight atomics (round-11 epilogue
// verbatim — locked).
__device__ __forceinline__ uint32_t swz64(int s, int c) {
    int p = s >> 1;
    int j = (((s & 1) << 2) | c) ^ (p & 7);
    return (uint32_t)(p * 128 + j * 16);
}

#define ATTN_SMEM (65536 + 65536 + 66048 + 1024 + 1024)

__global__ __launch_bounds__(512, 1)
void attn_kernel(float* __restrict__ attnw /* [16,1024,1024] */)
{
    extern __shared__ __align__(128) char smem[];
    char*  sKh = smem;                                   // 64KB
    char*  sKl = smem + 65536;                           // 64KB
    float* sS  = reinterpret_cast<float*>(smem + 131072); // 16 x 1032 f32
    char*  sQh = smem + 131072 + 66048;                  // 1KB
    char*  sQl = sQh + 1024;                             // 1KB

    const int bb   = blockIdx.x;
    const int tid  = threadIdx.x;
    const int lane = tid & 31;
    const int wid  = tid >> 5;      // 0..15

    const uint32_t skh = smem_u32(sKh), skl = smem_u32(sKl);
    const uint32_t sqh = smem_u32(sQh), sql = smem_u32(sQl);

    const int brow = (lane & 7) + ((lane >> 4) << 3);
    const int bcs  = (lane >> 3) & 1;
    const int arow = lane & 15;
    const int acs  = lane >> 4;

    // contiguous balanced unit range for this block
    const int u0 = (bb * 8192) / NBLK;
    const int u1 = ((bb + 1) * 8192) / NBLK;
    int cur_bh = -1;

    for (int u = u0; u < u1; u++) {
        const int bh   = u >> 6;
        const int wave = u & 63;
        const int b    = bh >> 3;
        const int h    = bh & 7;
        const int t0   = wave * 16;

        // ---- (re)load K[bh] hi/lo into packed-swizzled smem on bh change ----
        // Safe: prior unit's K ldmatrix reads completed before its scatter
        // sync; epilogues touch only sS/global. Q-fill sync below orders the
        // new K before any MMA read.
        if (bh != cur_bh) {
            cur_bh = bh;
            for (int idx = tid; idx < 4096; idx += 512) {
                int s = idx >> 2, c = idx & 3;
                uint32_t off = swz64(s, c);
                size_t gb = (((size_t)bh << 10) + s) * 32 + c * 8;
                *reinterpret_cast<uint4*>(sKh + off) =
                    *reinterpret_cast<const uint4*>(g_Kh + gb);
                *reinterpret_cast<uint4*>(sKl + off) =
                    *reinterpret_cast<const uint4*>(g_Kl + gb);
            }
        }

        const float* Vbase = g_QKV + (size_t)(512 + h * 32) + (size_t)b * 768;

        // ---- fill Q tile (16 rows x 32 bf16, hi+lo) ----
        if (tid < 128) {
            int a = tid >> 6, q = tid & 63;
            int r = q >> 2, c = q & 3;
            size_t gb = (((size_t)bh << 10) + t0 + r) * 32 + c * 8;
            const __nv_bfloat16* src = (a ? g_Ql : g_Qh) + gb;
            char* dst = (a ? sQl : sQh) + swz64(r, c);
            *reinterpret_cast<uint4*>(dst) = *reinterpret_cast<const uint4*>(src);
        }
        __syncthreads();   // K+Q ready; prev-unit sS reads complete

        // ---- MMA: warp wid covers score cols [wid*64, wid*64+64) ----
        uint32_t ah[2][4], al[2][4];
#pragma unroll
        for (int ks = 0; ks < 2; ks++) {
            uint32_t off = swz64(arow, 2 * ks + acs);
            ldmx4(ah[ks], sqh + off);
            ldmx4(al[ks], sql + off);
        }
        float d[8][4];
#pragma unroll
        for (int nt = 0; nt < 8; nt++)
#pragma unroll
            for (int j = 0; j < 4; j++) d[nt][j] = 0.f;

#pragma unroll
        for (int ks = 0; ks < 2; ks++) {
#pragma unroll
            for (int nt4 = 0; nt4 < 4; nt4++) {
                int srow = wid * 64 + nt4 * 16 + brow;
                uint32_t off = swz64(srow, 2 * ks + bcs);
                uint32_t bhf[4], blf[4];
                ldmx4(bhf, skh + off);
                ldmx4(blf, skl + off);
                mma_bf16(d[nt4 * 2 + 0], ah[ks], bhf[0], bhf[1]);
                mma_bf16(d[nt4 * 2 + 1], ah[ks], bhf[2], bhf[3]);
                mma_bf16(d[nt4 * 2 + 0], ah[ks], blf[0], blf[1]);
                mma_bf16(d[nt4 * 2 + 1], ah[ks], blf[2], blf[3]);
                mma_bf16(d[nt4 * 2 + 0], al[ks], bhf[0], bhf[1]);
                mma_bf16(d[nt4 * 2 + 1], al[ks], bhf[2], bhf[3]);
            }
        }

        // ---- scatter fragments to score buffer ----
        {
            int rr = lane >> 2;
            int cb = wid * 64 + 2 * (lane & 3);
#pragma unroll
            for (int nt = 0; nt < 8; nt++) {
                *reinterpret_cast<float2*>(&sS[rr * 1032 + cb + nt * 8]) =
                    make_float2(d[nt][0], d[nt][1]);
                *reinterpret_cast<float2*>(&sS[(rr + 8) * 1032 + cb + nt * 8]) =
                    make_float2(d[nt][2], d[nt][3]);
            }
        }
        __syncthreads();   // scores ready

        // ---- sparsemax + AV + avg attn weights: warp wid owns row t0+wid ----
        {
            float a[32];
#pragma unroll
            for (int c = 0; c < 8; c++) {
                float4 v4 = *reinterpret_cast<const float4*>(
                    &sS[wid * 1032 + c * 128 + lane * 4]);
                a[c * 4 + 0] = v4.x; a[c * 4 + 1] = v4.y;
                a[c * 4 + 2] = v4.z; a[c * 4 + 3] = v4.w;
            }

            // Michelot from tau = max(z) - 1 (valid support superset)
            float mx = a[0];
#pragma unroll
            for (int i = 1; i < 32; i++) mx = fmaxf(mx, a[i]);
#pragma unroll
            for (int o = 16; o > 0; o >>= 1)
                mx = fmaxf(mx, __shfl_xor_sync(0xffffffffu, mx, o));
            float tau = mx - 1.0f;
            int prevc = -1;

            for (int iter = 0; iter < 64; iter++) {
                float s = 0.f;
                int   c = 0;
#pragma unroll
                for (int i = 0; i < 32; i++) {
                    if (a[i] > tau) { s += a[i]; c++; }
                }
#pragma unroll
                for (int o = 16; o > 0; o >>= 1) {
                    s += __shfl_xor_sync(0xffffffffu, s, o);
                    c += __shfl_xor_sync(0xffffffffu, c, o);
                }
                if (c == prevc) break;
                tau = (s - 1.0f) / (float)c;
                prevc = c;
            }

            const int t = t0 + wid;
            float* awrow = attnw + ((size_t)b * TLEN + t) * SLEN;
            float outv = 0.f;
#pragma unroll
            for (int i = 0; i < 32; i++) {
                float w = (a[i] > tau) ? (a[i] - tau) : 0.f;
                unsigned m = __ballot_sync(0xffffffffu, w > 0.f);
                if (w > 0.f) {
                    int s_me = (i >> 2) * 128 + lane * 4 + (i & 3);
                    atomicAdd(awrow + s_me, 0.125f * w);
                }
                while (m) {
                    int j = __ffs(m) - 1;
                    m &= m - 1;
                    float wj = __shfl_sync(0xffffffffu, w, j);
                    int s = (i >> 2) * 128 + j * 4 + (i & 3);
                    outv = fmaf(wj, Vbase[(size_t)s * 12288 + lane], outv);
                }
            }
            g_ctx[((size_t)t * BSZ + b) * EMB + h * HD + lane] = outv;
        }
    }
}

// ---------------- launcher ---------------------------------------------------
extern "C" void kernel_launch(void* const* d_in, const int* in_sizes, int n_in,
                              void* d_out, int out_size)
{
    const float* query = (const float*)d_in[0];
    const float* key   = (const float*)d_in[1];
    const float* value = (const float*)d_in[2];
    const float* Win   = (const float*)d_in[3];
    const float* bin   = (const float*)d_in[4];
    const float* Wout  = (const float*)d_in[5];
    const float* bout  = (const float*)d_in[6];

    float* outp  = (float*)d_out;                         // [1024,16,256]
    float* attnw = outp + (size_t)MROWS * EMB;            // [16,1024,1024]

    cudaFuncSetAttribute(attn_kernel, cudaFuncAttributeMaxDynamicSharedMemorySize,
                         ATTN_SMEM);
    cudaFuncSetAttribute(gemm_mma<0>, cudaFuncAttributeMaxDynamicSharedMemorySize,
                         GM_SMEM);
    cudaFuncSetAttribute(gemm_mma<1>, cudaFuncAttributeMaxDynamicSharedMemorySize,
                         GM_SMEM);

    // 1) zero averaged attention-weights output (sparse atomics accumulate into it)
    zero_f4<<<2048, 256>>>((float4*)attnw, (int)((size_t)BSZ * TLEN * SLEN / 4));

    // 2) QKV projection (M=16384, N=768, K=256) + bf16 hi/lo emit for Q,K
    gemm_mma<0><<<dim3(6, MROWS / 128), 256, GM_SMEM>>>(query, key, value, Win, bin, nullptr);

    // 3) fused attention: persistent units, HMMA scores + sparsemax + AV
    attn_kernel<<<NBLK, 512, ATTN_SMEM>>>(attnw);

    // 4) output projection (M=16384, N=256, K=256)
    gemm_mma<1><<<dim3(2, MROWS / 128), 256, GM_SMEM>>>(nullptr, nullptr, nullptr, Wout, bout, outp);
}

// round 15
// speedup vs baseline: 1.4513x; 1.0490x over previous
#include <cuda_runtime.h>
#include <cuda_bf16.h>
#include <cstdint>

// Problem constants
#define TLEN   1024
#define SLEN   1024
#define BSZ    16
#define EMB    256
#define NH     8
#define HD     32
#define BH     (BSZ*NH)        // 128
#define MROWS  (TLEN*BSZ)      // 16384
#define QSCALE 0.17677669529663688f   // 1/sqrt(32)
#define NBLK   148             // persistent attn grid (one CTA per SM)
#define LCAP   1024            // support-list capacity per row (worst case)

typedef unsigned long long u64;

__device__ __forceinline__ uint32_t smem_u32(const void* p) {
    uint32_t a;
    asm("{ .reg .u64 t; cvta.to.shared.u64 t, %1; cvt.u32.u64 %0, t; }"
        : "=r"(a) : "l"(p));
    return a;
}

// ---- mma.sync helpers (base ISA; sm_103 target has no tcgen05) --------------
__device__ __forceinline__ void ldmx4(uint32_t r[4], uint32_t addr) {
    asm volatile("ldmatrix.sync.aligned.m8n8.x4.shared.b16 {%0,%1,%2,%3}, [%4];"
                 : "=r"(r[0]), "=r"(r[1]), "=r"(r[2]), "=r"(r[3]) : "r"(addr));
}
__device__ __forceinline__ void mma_bf16(float d[4], const uint32_t a[4],
                                         uint32_t b0, uint32_t b1) {
    asm volatile(
        "mma.sync.aligned.m16n8k16.row.col.f32.bf16.bf16.f32 "
        "{%0,%1,%2,%3}, {%4,%5,%6,%7}, {%8,%9}, {%0,%1,%2,%3};"
        : "+f"(d[0]), "+f"(d[1]), "+f"(d[2]), "+f"(d[3])
        : "r"(a[0]), "r"(a[1]), "r"(a[2]), "r"(a[3]), "r"(b0), "r"(b1));
}

// ---------------- scratch (device globals; no allocation allowed) ----------
__device__ float g_ctx[(size_t)MROWS * EMB];   // [t*16+b][h*32+d]
// bf16 hi/lo splits of Q (scaled) and K, per-bh contiguous: [bh][t or s][32]
__device__ __align__(16) __nv_bfloat16 g_Qh[(size_t)BH*1024*32];
__device__ __align__(16) __nv_bfloat16 g_Ql[(size_t)BH*1024*32];
__device__ __align__(16) __nv_bfloat16 g_Kh[(size_t)BH*1024*32];
__device__ __align__(16) __nv_bfloat16 g_Kl[(size_t)BH*1024*32];
// compact fp32 V: [bh][s][32]
__device__ __align__(16) float g_Vc[(size_t)BH*1024*32];
// sparse support lists: per (bh,t) row, up to LCAP (w,s) entries + count
__device__ __align__(16) float2 g_list[(size_t)BH*1024*LCAP];
__device__ int g_cnt[BH*1024];

// ---------------- zero kernel ----------------------------------------------
__global__ void zero_f4(float4* __restrict__ p, int n4) {
    int i = blockIdx.x * blockDim.x + threadIdx.x;
    int stride = gridDim.x * blockDim.x;
    float4 z = make_float4(0.f, 0.f, 0.f, 0.f);
    for (; i < n4; i += stride) p[i] = z;
}

// ---------------- bf16-split HMMA GEMM:  out = X.W^T + b --------------------
#define GM_SMEM 65536

__device__ __forceinline__ void conv_store_g(float4 x, char* hi, char* lo,
                                             int row, int kg4) {
    __nv_bfloat162 h01 = __floats2bfloat162_rn(x.x, x.y);
    __nv_bfloat162 h23 = __floats2bfloat162_rn(x.z, x.w);
    float r0 = x.x - __bfloat162float(h01.x);
    float r1 = x.y - __bfloat162float(h01.y);
    float r2 = x.z - __bfloat162float(h23.x);
    float r3 = x.w - __bfloat162float(h23.y);
    __nv_bfloat162 l01 = __floats2bfloat162_rn(r0, r1);
    __nv_bfloat162 l23 = __floats2bfloat162_rn(r2, r3);
    int c  = kg4 >> 3;
    int sw = row * 128 + ((c ^ (row & 7)) << 4) + ((kg4 & 7) * 2);
    u64 hp = (u64)(*reinterpret_cast<uint32_t*>(&h01)) |
             ((u64)(*reinterpret_cast<uint32_t*>(&h23)) << 32);
    u64 lp = (u64)(*reinterpret_cast<uint32_t*>(&l01)) |
             ((u64)(*reinterpret_cast<uint32_t*>(&l23)) << 32);
    *reinterpret_cast<u64*>(hi + sw) = hp;
    *reinterpret_cast<u64*>(lo + sw) = lp;
}

template<int MODE>
__global__ __launch_bounds__(256)
void gemm_mma(const float* __restrict__ Xq, const float* __restrict__ Xk,
              const float* __restrict__ Xv, const float* __restrict__ W,
              const float* __restrict__ bias, float* __restrict__ outp)
{
    extern __shared__ __align__(128) char smem[];
    char* Ah = smem;
    char* Al = smem + 16384;
    char* Bh = smem + 32768;
    char* Bl = smem + 49152;

    const int tid  = threadIdx.x;
    const int lane = tid & 31;
    const int wid  = tid >> 5;
    const int mw   = (wid & 3) * 32;
    const int nw   = (wid >> 2) * 64;
    const int n0 = blockIdx.x * 128;
    const int m0 = blockIdx.y * 128;

    const float* X;
    if (MODE == 0) {
        int sec = n0 >> 8;
        X = (sec == 0) ? Xq : (sec == 1 ? Xk : Xv);
    } else {
        X = g_ctx;
    }

    const uint32_t sA = smem_u32(Ah), sAl = smem_u32(Al);
    const uint32_t sB = smem_u32(Bh), sBl = smem_u32(Bl);

    float d[2][8][4];
#pragma unroll
    for (int mt = 0; mt < 2; mt++)
#pragma unroll
        for (int nt = 0; nt < 8; nt++)
#pragma unroll
            for (int j = 0; j < 4; j++) d[mt][nt][j] = 0.f;

    const int arow = lane & 15;
    const int acs  = lane >> 4;
    const int brow = (lane & 7) + ((lane >> 4) << 3);
    const int bcs  = (lane >> 3) & 1;
    const int lxor = lane & 7;

    for (int kc = 0; kc < 4; kc++) {
#pragma unroll
        for (int g = tid, it = 0; it < 8; g += 256, it++) {
            int row = g >> 4;
            int kg4 = (g & 15) * 4;
            float4 xa = *reinterpret_cast<const float4*>(
                X + (size_t)(m0 + row) * 256 + kc * 64 + kg4);
            conv_store_g(xa, Ah, Al, row, kg4);
            float4 xb = *reinterpret_cast<const float4*>(
                W + (size_t)(n0 + row) * 256 + kc * 64 + kg4);
            conv_store_g(xb, Bh, Bl, row, kg4);
        }
        __syncthreads();

#pragma unroll
        for (int ks = 0; ks < 4; ks++) {
            uint32_t ah[2][4], al[2][4], bh[4][4], bl[4][4];
#pragma unroll
            for (int mt = 0; mt < 2; mt++) {
                int row = mw + mt * 16 + arow;
                uint32_t off = (uint32_t)(row * 128 + (((2 * ks + acs) ^ lxor) << 4));
                ldmx4(ah[mt], sA + off);
                ldmx4(al[mt], sAl + off);
            }
#pragma unroll
            for (int nt4 = 0; nt4 < 4; nt4++) {
                int row = nw + nt4 * 16 + brow;
                uint32_t off = (uint32_t)(row * 128 + (((2 * ks + bcs) ^ lxor) << 4));
                ldmx4(bh[nt4], sB + off);
                ldmx4(bl[nt4], sBl + off);
            }
#pragma unroll
            for (int mt = 0; mt < 2; mt++)
#pragma unroll
                for (int nt4 = 0; nt4 < 4; nt4++) {
                    mma_bf16(d[mt][nt4 * 2 + 0], ah[mt], bh[nt4][0], bh[nt4][1]);
                    mma_bf16(d[mt][nt4 * 2 + 1], ah[mt], bh[nt4][2], bh[nt4][3]);
                    mma_bf16(d[mt][nt4 * 2 + 0], ah[mt], bl[nt4][0], bl[nt4][1]);
                    mma_bf16(d[mt][nt4 * 2 + 1], ah[mt], bl[nt4][2], bl[nt4][3]);
                    mma_bf16(d[mt][nt4 * 2 + 0], al[mt], bh[nt4][0], bh[nt4][1]);
                    mma_bf16(d[mt][nt4 * 2 + 1], al[mt], bh[nt4][2], bh[nt4][3]);
                }
        }
        __syncthreads();
    }

    // ---- epilogue ----
    const float scl = (MODE == 0 && n0 < 256) ? QSCALE : 1.0f;
    const int qrow = lane >> 2;
    const int qcol = (lane & 3) * 2;
#pragma unroll
    for (int mt = 0; mt < 2; mt++) {
#pragma unroll
        for (int nt = 0; nt < 8; nt++) {
            int n = n0 + nw + nt * 8 + qcol;
            float2 bv = *reinterpret_cast<const float2*>(bias + n);
            int r0 = m0 + mw + mt * 16 + qrow;
#pragma unroll
            for (int hfl = 0; hfl < 2; hfl++) {
                int r = r0 + hfl * 8;
                float2 v;
                v.x = (d[mt][nt][hfl * 2 + 0] + bv.x) * scl;
                v.y = (d[mt][nt][hfl * 2 + 1] + bv.y) * scl;
                if (MODE == 1) {
                    *reinterpret_cast<float2*>(outp + (size_t)r * 256 + n) = v;
                } else {
                    int sec = n >> 8;
                    int hh = (n >> 5) & 7, dd = n & 31;
                    int tt = r >> 4,      bb = r & 15;
                    size_t base = (((size_t)(bb * 8 + hh) << 10) + tt) * 32 + dd;
                    if (sec < 2) {
                        // bf16 hi/lo split for q (scaled) and k
                        __nv_bfloat162 hi2 = __floats2bfloat162_rn(v.x, v.y);
                        float rx = v.x - __bfloat162float(hi2.x);
                        float ry = v.y - __bfloat162float(hi2.y);
                        __nv_bfloat162 lo2 = __floats2bfloat162_rn(rx, ry);
                        if (sec == 0) {
                            *reinterpret_cast<__nv_bfloat162*>(g_Qh + base) = hi2;
                            *reinterpret_cast<__nv_bfloat162*>(g_Ql + base) = lo2;
                        } else {
                            *reinterpret_cast<__nv_bfloat162*>(g_Kh + base) = hi2;
                            *reinterpret_cast<__nv_bfloat162*>(g_Kl + base) = lo2;
                        }
                    } else {
                        // compact fp32 V
                        *reinterpret_cast<float2*>(g_Vc + base) = v;
                    }
                }
            }
        }
    }
}

// ---------------- k1: persistent attn — HMMA scores + sparsemax + lists -----
// 148 persistent blocks, 512 threads (16 warps). Work unit = (bh, wave of 16
// t-rows). Per unit: HMMA scores -> 16x1024 smem buffer; warp w owns row w:
// Michelot sparsemax + avg-attn-weight atomics + compacted (w,s) list to
// global (AV moved to av_kernel — kills the serial V-LDG chain here).
__device__ __forceinline__ uint32_t swz64(int s, int c) {
    int p = s >> 1;
    int j = (((s & 1) << 2) | c) ^ (p & 7);
    return (uint32_t)(p * 128 + j * 16);
}

#define ATTN_SMEM (65536 + 65536 + 66048 + 1024 + 1024)

__global__ __launch_bounds__(512, 1)
void attn_kernel(float* __restrict__ attnw /* [16,1024,1024] */)
{
    extern __shared__ __align__(128) char smem[];
    char*  sKh = smem;                                   // 64KB
    char*  sKl = smem + 65536;                           // 64KB
    float* sS  = reinterpret_cast<float*>(smem + 131072); // 16 x 1032 f32
    char*  sQh = smem + 131072 + 66048;                  // 1KB
    char*  sQl = sQh + 1024;                             // 1KB

    const int bb   = blockIdx.x;
    const int tid  = threadIdx.x;
    const int lane = tid & 31;
    const int wid  = tid >> 5;      // 0..15

    const uint32_t skh = smem_u32(sKh), skl = smem_u32(sKl);
    const uint32_t sqh = smem_u32(sQh), sql = smem_u32(sQl);

    const int brow = (lane & 7) + ((lane >> 4) << 3);
    const int bcs  = (lane >> 3) & 1;
    const int arow = lane & 15;
    const int acs  = lane >> 4;

    const int u0 = (bb * 8192) / NBLK;
    const int u1 = ((bb + 1) * 8192) / NBLK;
    int cur_bh = -1;

    for (int u = u0; u < u1; u++) {
        const int bh   = u >> 6;
        const int wave = u & 63;
        const int b    = bh >> 3;
        const int t0   = wave * 16;

        if (bh != cur_bh) {
            cur_bh = bh;
            for (int idx = tid; idx < 4096; idx += 512) {
                int s = idx >> 2, c = idx & 3;
                uint32_t off = swz64(s, c);
                size_t gb = (((size_t)bh << 10) + s) * 32 + c * 8;
                *reinterpret_cast<uint4*>(sKh + off) =
                    *reinterpret_cast<const uint4*>(g_Kh + gb);
                *reinterpret_cast<uint4*>(sKl + off) =
                    *reinterpret_cast<const uint4*>(g_Kl + gb);
            }
        }

        // ---- fill Q tile (16 rows x 32 bf16, hi+lo) ----
        if (tid < 128) {
            int a = tid >> 6, q = tid & 63;
            int r = q >> 2, c = q & 3;
            size_t gb = (((size_t)bh << 10) + t0 + r) * 32 + c * 8;
            const __nv_bfloat16* src = (a ? g_Ql : g_Qh) + gb;
            char* dst = (a ? sQl : sQh) + swz64(r, c);
            *reinterpret_cast<uint4*>(dst) = *reinterpret_cast<const uint4*>(src);
        }
        __syncthreads();   // K+Q ready; prev-unit sS reads complete

        // ---- MMA: warp wid covers score cols [wid*64, wid*64+64) ----
        uint32_t ah[2][4], al[2][4];
#pragma unroll
        for (int ks = 0; ks < 2; ks++) {
            uint32_t off = swz64(arow, 2 * ks + acs);
            ldmx4(ah[ks], sqh + off);
            ldmx4(al[ks], sql + off);
        }
        float d[8][4];
#pragma unroll
        for (int nt = 0; nt < 8; nt++)
#pragma unroll
            for (int j = 0; j < 4; j++) d[nt][j] = 0.f;

#pragma unroll
        for (int ks = 0; ks < 2; ks++) {
#pragma unroll
            for (int nt4 = 0; nt4 < 4; nt4++) {
                int srow = wid * 64 + nt4 * 16 + brow;
                uint32_t off = swz64(srow, 2 * ks + bcs);
                uint32_t bhf[4], blf[4];
                ldmx4(bhf, skh + off);
                ldmx4(blf, skl + off);
                mma_bf16(d[nt4 * 2 + 0], ah[ks], bhf[0], bhf[1]);
                mma_bf16(d[nt4 * 2 + 1], ah[ks], bhf[2], bhf[3]);
                mma_bf16(d[nt4 * 2 + 0], ah[ks], blf[0], blf[1]);
                mma_bf16(d[nt4 * 2 + 1], ah[ks], blf[2], blf[3]);
                mma_bf16(d[nt4 * 2 + 0], al[ks], bhf[0], bhf[1]);
                mma_bf16(d[nt4 * 2 + 1], al[ks], bhf[2], bhf[3]);
            }
        }

        // ---- scatter fragments to score buffer ----
        {
            int rr = lane >> 2;
            int cb = wid * 64 + 2 * (lane & 3);
#pragma unroll
            for (int nt = 0; nt < 8; nt++) {
                *reinterpret_cast<float2*>(&sS[rr * 1032 + cb + nt * 8]) =
                    make_float2(d[nt][0], d[nt][1]);
                *reinterpret_cast<float2*>(&sS[(rr + 8) * 1032 + cb + nt * 8]) =
                    make_float2(d[nt][2], d[nt][3]);
            }
        }
        __syncthreads();   // scores ready

        // ---- sparsemax + attnw atomics + support list: warp wid = row ----
        {
            float a[32];
#pragma unroll
            for (int c = 0; c < 8; c++) {
                float4 v4 = *reinterpret_cast<const float4*>(
                    &sS[wid * 1032 + c * 128 + lane * 4]);
                a[c * 4 + 0] = v4.x; a[c * 4 + 1] = v4.y;
                a[c * 4 + 2] = v4.z; a[c * 4 + 3] = v4.w;
            }

            // Michelot from tau = max(z) - 1 (valid support superset)
            float mx = a[0];
#pragma unroll
            for (int i = 1; i < 32; i++) mx = fmaxf(mx, a[i]);
#pragma unroll
            for (int o = 16; o > 0; o >>= 1)
                mx = fmaxf(mx, __shfl_xor_sync(0xffffffffu, mx, o));
            float tau = mx - 1.0f;
            int prevc = -1;

            for (int iter = 0; iter < 64; iter++) {
                float s = 0.f;
                int   c = 0;
#pragma unroll
                for (int i = 0; i < 32; i++) {
                    if (a[i] > tau) { s += a[i]; c++; }
                }
#pragma unroll
                for (int o = 16; o > 0; o >>= 1) {
                    s += __shfl_xor_sync(0xffffffffu, s, o);
                    c += __shfl_xor_sync(0xffffffffu, c, o);
                }
                if (c == prevc) break;
                tau = (s - 1.0f) / (float)c;
                prevc = c;
            }

            const int t = t0 + wid;
            float* awrow = attnw + ((size_t)b * TLEN + t) * SLEN;
            size_t lbase = ((size_t)((bh << 10) + t)) << 10;   // *LCAP
            int cnt = 0;
#pragma unroll
            for (int i = 0; i < 32; i++) {
                float w = a[i] - tau;
                bool act = w > 0.f;
                unsigned m = __ballot_sync(0xffffffffu, act);
                if (act) {
                    int s_me = (i >> 2) * 128 + lane * 4 + (i & 3);
                    atomicAdd(awrow + s_me, 0.125f * w);
                    int pos = cnt + __popc(m & ((1u << lane) - 1u));
                    g_list[lbase + pos] = make_float2(w, __int_as_float(s_me));
                }
                cnt += __popc(m);
            }
            if (lane == 0) g_cnt[(bh << 10) + t] = cnt;
        }
    }
}

// ---------------- k2: AV gather with V resident in smem ---------------------
// 128 blocks (one per bh), 512 threads. V[bh] (1024x32 fp32, 128KB) in smem;
// per row t: read compacted (w,s) list lane-parallel, broadcast-accumulate
// from smem (29-cyc LDS instead of 250-cyc LDG).
#define AV_SMEM 131072

__global__ __launch_bounds__(512, 1)
void av_kernel()
{
    extern __shared__ __align__(16) float sV[];   // [1024][32]
    const int bh   = blockIdx.x;
    const int tid  = threadIdx.x;
    const int lane = tid & 31;
    const int wid  = tid >> 5;
    const int b    = bh >> 3;
    const int h    = bh & 7;

    for (int i = tid; i < 8192; i += 512)
        reinterpret_cast<float4*>(sV)[i] =
            reinterpret_cast<const float4*>(g_Vc + ((size_t)bh << 15))[i];
    __syncthreads();

    for (int t = wid; t < 1024; t += 16) {
        const int cnt = g_cnt[(bh << 10) + t];
        const size_t lbase = ((size_t)((bh << 10) + t)) << 10;
        float outv = 0.f;
        for (int c0 = 0; c0 < cnt; c0 += 32) {
            int k = c0 + lane;
            float2 e = make_float2(0.f, 0.f);
            if (k < cnt) e = g_list[lbase + k];
            int n = min(cnt - c0, 32);
            for (int j = 0; j < n; j++) {
                float w = __shfl_sync(0xffffffffu, e.x, j);
                int   s = __shfl_sync(0xffffffffu, __float_as_int(e.y), j);
                outv = fmaf(w, sV[s * 32 + lane], outv);
            }
        }
        g_ctx[((size_t)t * BSZ + b) * EMB + h * HD + lane] = outv;
    }
}

// ---------------- launcher ---------------------------------------------------
extern "C" void kernel_launch(void* const* d_in, const int* in_sizes, int n_in,
                              void* d_out, int out_size)
{
    const float* query = (const float*)d_in[0];
    const float* key   = (const float*)d_in[1];
    const float* value = (const float*)d_in[2];
    const float* Win   = (const float*)d_in[3];
    const float* bin   = (const float*)d_in[4];
    const float* Wout  = (const float*)d_in[5];
    const float* bout  = (const float*)d_in[6];

    float* outp  = (float*)d_out;                         // [1024,16,256]
    float* attnw = outp + (size_t)MROWS * EMB;            // [16,1024,1024]

    cudaFuncSetAttribute(attn_kernel, cudaFuncAttributeMaxDynamicSharedMemorySize,
                         ATTN_SMEM);
    cudaFuncSetAttribute(av_kernel, cudaFuncAttributeMaxDynamicSharedMemorySize,
                         AV_SMEM);
    cudaFuncSetAttribute(gemm_mma<0>, cudaFuncAttributeMaxDynamicSharedMemorySize,
                         GM_SMEM);
    cudaFuncSetAttribute(gemm_mma<1>, cudaFuncAttributeMaxDynamicSharedMemorySize,
                         GM_SMEM);

    // 1) zero averaged attention-weights output (sparse atomics accumulate into it)
    zero_f4<<<2048, 256>>>((float4*)attnw, (int)((size_t)BSZ * TLEN * SLEN / 4));

    // 2) QKV projection: bf16 hi/lo emit for Q,K + compact fp32 V
    gemm_mma<0><<<dim3(6, MROWS / 128), 256, GM_SMEM>>>(query, key, value, Win, bin, nullptr);

    // 3) k1: HMMA scores + sparsemax + attnw atomics + support lists
    attn_kernel<<<NBLK, 512, ATTN_SMEM>>>(attnw);

    // 4) k2: AV gather with smem-resident V -> g_ctx
    av_kernel<<<BH, 512, AV_SMEM>>>();

    // 5) output projection (M=16384, N=256, K=256)
    gemm_mma<1><<<dim3(2, MROWS / 128), 256, GM_SMEM>>>(nullptr, nullptr, nullptr, Wout, bout, outp);
}